// round 1
// baseline (speedup 1.0000x reference)
#include <cuda_runtime.h>
#include <math.h>

#define Bn 512
#define Tn 256
#define Cn 192
#define Hn 64

// Scratch (device globals are the sanctioned alloc-free mechanism)
__device__ float g_qkv[(size_t)Bn * Tn * 192];   // [b][t][ q(0:64) | k(64:128) | v(128:192) ]
__device__ float g_pos[Tn * 128];                // [t][ pos_k(0:64) | pos_q(64:128) ]
__device__ float g_bias[Tn * Tn];                // bias[q_row][k_col]

// ---------------------------------------------------------------------------
// Kernel 1: QKV projection GEMM.  A = x [B*T, 192], W in {Wq,Wk,Wv} [192,64].
// BM=128, BN=64, BK=16, 256 threads, 8x4 register microtile.
// ---------------------------------------------------------------------------
__global__ __launch_bounds__(256) void qkv_kernel(const float* __restrict__ x,
                                                  const float* __restrict__ Wq,
                                                  const float* __restrict__ Wk,
                                                  const float* __restrict__ Wv) {
    __shared__ float A_s[128][17];   // padded: avoid bank conflicts on a[] reads
    __shared__ float B_s[16][68];    // padded for float4 store alignment

    const int sel = blockIdx.y;      // 0->q, 1->k, 2->v
    const float* __restrict__ W = (sel == 0) ? Wq : ((sel == 1) ? Wk : Wv);

    const int row0 = blockIdx.x * 128;
    const int tid = threadIdx.x;
    const int tx = tid & 15;         // col group
    const int ty = tid >> 4;         // row group (0..15), 8 rows each

    float acc[8][4];
#pragma unroll
    for (int i = 0; i < 8; i++)
#pragma unroll
        for (int j = 0; j < 4; j++) acc[i][j] = 0.0f;

    for (int k0 = 0; k0 < 192; k0 += 16) {
        // Load A tile: 128x16 floats = 512 float4, 2 per thread
#pragma unroll
        for (int t = 0; t < 2; t++) {
            int f = tid + t * 256;          // 0..511
            int r = f >> 2;
            int c4 = f & 3;
            float4 val = *(const float4*)(x + (size_t)(row0 + r) * 192 + k0 + c4 * 4);
            A_s[r][c4 * 4 + 0] = val.x;
            A_s[r][c4 * 4 + 1] = val.y;
            A_s[r][c4 * 4 + 2] = val.z;
            A_s[r][c4 * 4 + 3] = val.w;
        }
        // Load B tile: 16x64 floats = 256 float4, 1 per thread
        {
            int kk = tid >> 4;
            int c4 = tid & 15;
            float4 val = *(const float4*)(W + (size_t)(k0 + kk) * 64 + c4 * 4);
            B_s[kk][c4 * 4 + 0] = val.x;
            B_s[kk][c4 * 4 + 1] = val.y;
            B_s[kk][c4 * 4 + 2] = val.z;
            B_s[kk][c4 * 4 + 3] = val.w;
        }
        __syncthreads();

#pragma unroll
        for (int kk = 0; kk < 16; kk++) {
            float a[8], b[4];
#pragma unroll
            for (int i = 0; i < 8; i++) a[i] = A_s[ty * 8 + i][kk];
#pragma unroll
            for (int j = 0; j < 4; j++) b[j] = B_s[kk][tx + 16 * j];
#pragma unroll
            for (int i = 0; i < 8; i++)
#pragma unroll
                for (int j = 0; j < 4; j++) acc[i][j] = fmaf(a[i], b[j], acc[i][j]);
        }
        __syncthreads();
    }

    // Store: output column for thread = tx + 16*j
#pragma unroll
    for (int i = 0; i < 8; i++) {
        size_t rbase = (size_t)(row0 + ty * 8 + i) * 192 + sel * 64;
#pragma unroll
        for (int j = 0; j < 4; j++) {
            g_qkv[rbase + tx + 16 * j] = acc[i][j];
        }
    }
}

// ---------------------------------------------------------------------------
// Kernel 2: positional projections  pos_k = pe@Wk, pos_q = pe@Wq  (tiny)
// ---------------------------------------------------------------------------
__global__ __launch_bounds__(256) void pos_kernel(const float* __restrict__ pe,
                                                  const float* __restrict__ Wk,
                                                  const float* __restrict__ Wq) {
    int idx = blockIdx.x * 256 + threadIdx.x;   // 0..32767
    int t = idx >> 7;
    int j = idx & 127;
    const float* __restrict__ W = (j < 64) ? Wk : Wq;
    int col = j & 63;
    float s = 0.0f;
#pragma unroll 4
    for (int c = 0; c < 192; c++) s = fmaf(pe[t * 192 + c], W[c * 64 + col], s);
    g_pos[idx] = s;
}

// ---------------------------------------------------------------------------
// Kernel 3: bias[i][j] = pos_k[i] . pos_q[j]   (tiny)
// ---------------------------------------------------------------------------
__global__ __launch_bounds__(256) void bias_kernel() {
    int i = blockIdx.x;
    int j = threadIdx.x;
    float s = 0.0f;
#pragma unroll 4
    for (int h = 0; h < 64; h++)
        s = fmaf(g_pos[i * 128 + h], g_pos[j * 128 + 64 + h], s);
    g_bias[i * 256 + j] = s;
}

// ---------------------------------------------------------------------------
// Kernel 4: causal attention per batch.  One CTA per batch, 8 warps.
// q/k/v staged in smem (k padded 65/row -> conflict-free); warp handles
// 4-row groups (32 score accumulators); softmax via warp shuffles; PV via
// per-warp p staging in smem.
// ---------------------------------------------------------------------------
__global__ __launch_bounds__(256) void attn_kernel(float* __restrict__ out) {
    extern __shared__ float sm[];
    float* q_s = sm;                    // [256][64]     16384
    float* k_s = sm + 16384;            // [256][65]     16640
    float* v_s = k_s + 16640;           // [256][64]     16384
    float* p_s = v_s + 16384;           // [8 warps][4 rows][256]  8192
    // total 57600 floats = 230400 bytes

    const int b = blockIdx.x;
    const int tid = threadIdx.x;
    const int lane = tid & 31;
    const int w = tid >> 5;

    // Stage q/k/v for this batch: 256 rows x 192 floats = 12288 float4
    const float* __restrict__ base = g_qkv + (size_t)b * Tn * 192;
    for (int f = tid; f < 12288; f += 256) {
        int row = f / 48;
        int c4 = f % 48;
        float4 val = *(const float4*)(base + row * 192 + c4 * 4);
        int seg = c4 >> 4;              // 0=q, 1=k, 2=v (16-float4 aligned segments)
        int c = (c4 * 4) & 63;
        if (seg == 0) {
            float* d = &q_s[row * 64 + c];
            d[0] = val.x; d[1] = val.y; d[2] = val.z; d[3] = val.w;
        } else if (seg == 1) {
            float* d = &k_s[row * 65 + c];
            d[0] = val.x; d[1] = val.y; d[2] = val.z; d[3] = val.w;
        } else {
            float* d = &v_s[row * 64 + c];
            d[0] = val.x; d[1] = val.y; d[2] = val.z; d[3] = val.w;
        }
    }
    __syncthreads();

    const float scale = rsqrtf((float)Cn);
    float* pw = p_s + w * 1024;         // this warp's p staging [4][256]

    // 64 groups of 4 rows; warp w takes groups w, w+8, ...
    for (int g = w; g < 64; g += 8) {
        const int row0 = g * 4;
        const int nIg = (row0 + 3) / 32 + 1;   // # of 32-wide j blocks with any valid j

        float s[4][8];
#pragma unroll
        for (int r = 0; r < 4; r++)
#pragma unroll
            for (int i = 0; i < 8; i++) s[r][i] = 0.0f;

        // Scores: s[r][i] = q[row0+r] . k[i*32+lane]
        for (int h = 0; h < 64; h++) {
            float q0 = q_s[(row0 + 0) * 64 + h];
            float q1 = q_s[(row0 + 1) * 64 + h];
            float q2 = q_s[(row0 + 2) * 64 + h];
            float q3 = q_s[(row0 + 3) * 64 + h];
#pragma unroll
            for (int i = 0; i < 8; i++) {
                if (i < nIg) {
                    float kv = k_s[(i * 32 + lane) * 65 + h];
                    s[0][i] = fmaf(q0, kv, s[0][i]);
                    s[1][i] = fmaf(q1, kv, s[1][i]);
                    s[2][i] = fmaf(q2, kv, s[2][i]);
                    s[3][i] = fmaf(q3, kv, s[3][i]);
                }
            }
        }

        // Softmax per row (scale + bias + causal mask), normalized p into smem
#pragma unroll
        for (int r = 0; r < 4; r++) {
            const int row = row0 + r;
            const float* __restrict__ brow = g_bias + row * 256;
            float m = -1e30f;
#pragma unroll
            for (int i = 0; i < 8; i++) {
                float val;
                if (i < nIg) {
                    int j = i * 32 + lane;
                    val = fmaf(s[r][i], scale, brow[j]);
                    if (j > row) val = -1e30f;
                } else {
                    val = -1e30f;
                }
                s[r][i] = val;
                m = fmaxf(m, val);
            }
#pragma unroll
            for (int off = 16; off > 0; off >>= 1)
                m = fmaxf(m, __shfl_xor_sync(0xffffffffu, m, off));

            float lsum = 0.0f;
#pragma unroll
            for (int i = 0; i < 8; i++) {
                float e = __expf(s[r][i] - m);   // masked entries -> exp(-1e30) = 0
                s[r][i] = e;
                lsum += e;
            }
#pragma unroll
            for (int off = 16; off > 0; off >>= 1)
                lsum += __shfl_xor_sync(0xffffffffu, lsum, off);

            float inv = 1.0f / lsum;
#pragma unroll
            for (int i = 0; i < 8; i++) {
                if (i < nIg) pw[r * 256 + i * 32 + lane] = s[r][i] * inv;
            }
        }
        __syncwarp();

        // PV: out[r][h] = sum_j p[r][j] * v[j][h] ; lane owns h=lane, lane+32
        float o00 = 0.f, o01 = 0.f, o10 = 0.f, o11 = 0.f;
        float o20 = 0.f, o21 = 0.f, o30 = 0.f, o31 = 0.f;
        const int jEnd = nIg * 32;       // entries beyond row are exactly 0 in pw
        for (int j = 0; j < jEnd; j++) {
            float v0 = v_s[j * 64 + lane];
            float v1 = v_s[j * 64 + lane + 32];
            float p0 = pw[0 * 256 + j];
            float p1 = pw[1 * 256 + j];
            float p2 = pw[2 * 256 + j];
            float p3 = pw[3 * 256 + j];
            o00 = fmaf(p0, v0, o00); o01 = fmaf(p0, v1, o01);
            o10 = fmaf(p1, v0, o10); o11 = fmaf(p1, v1, o11);
            o20 = fmaf(p2, v0, o20); o21 = fmaf(p2, v1, o21);
            o30 = fmaf(p3, v0, o30); o31 = fmaf(p3, v1, o31);
        }

        float* ob = out + ((size_t)b * Tn + row0) * 64;
        ob[0 * 64 + lane] = o00; ob[0 * 64 + lane + 32] = o01;
        ob[1 * 64 + lane] = o10; ob[1 * 64 + lane + 32] = o11;
        ob[2 * 64 + lane] = o20; ob[2 * 64 + lane + 32] = o21;
        ob[3 * 64 + lane] = o30; ob[3 * 64 + lane + 32] = o31;
        __syncwarp();   // pw reused next group
    }
}

// ---------------------------------------------------------------------------
extern "C" void kernel_launch(void* const* d_in, const int* in_sizes, int n_in,
                              void* d_out, int out_size) {
    const float* x  = (const float*)d_in[0];
    const float* Wk = (const float*)d_in[1];
    const float* Wq = (const float*)d_in[2];
    const float* Wv = (const float*)d_in[3];
    const float* pe = (const float*)d_in[4];
    float* out = (float*)d_out;

    (void)in_sizes; (void)n_in; (void)out_size;

    static bool attr_set = false;
    if (!attr_set) {
        cudaFuncSetAttribute(attn_kernel,
                             cudaFuncAttributeMaxDynamicSharedMemorySize,
                             230400);
        attr_set = true;
    }

    dim3 qkv_grid(1024, 3);
    qkv_kernel<<<qkv_grid, 256>>>(x, Wq, Wk, Wv);

    pos_kernel<<<128, 256>>>(pe, Wk, Wq);
    bias_kernel<<<256, 256>>>();

    attn_kernel<<<512, 256, 230400>>>(out);
}

// round 2
// speedup vs baseline: 2.3455x; 2.3455x over previous
#include <cuda_runtime.h>
#include <math.h>
#include <stdint.h>

#define Bn 512
#define Tn 256
#define Cn 192
#define Hn 64
#define NROWS (Bn * Tn)

// Scratch (device globals = sanctioned alloc-free mechanism)
__device__ float g_q[(size_t)NROWS * Hn];        // [b*t][h] row-major
__device__ float g_kT[(size_t)Bn * Hn * Tn];     // [b][h][t] transposed
__device__ float g_vT[(size_t)Bn * Hn * Tn];     // [b][h][t] transposed
__device__ float g_pos[Tn * 128];                // [t][ pos_k | pos_q ]
__device__ float g_bias[Tn * Tn];

// ---------------------------------------------------------------------------
__device__ __forceinline__ unsigned f2tf(float f) {
    unsigned u;
    asm("cvt.rna.tf32.f32 %0, %1;" : "=r"(u) : "f"(f));
    return u;
}

__device__ __forceinline__ void mma_tf32(float c[4], const unsigned a[4],
                                         unsigned b0, unsigned b1) {
    asm volatile(
        "mma.sync.aligned.m16n8k8.row.col.f32.tf32.tf32.f32 "
        "{%0,%1,%2,%3}, {%4,%5,%6,%7}, {%8,%9}, {%0,%1,%2,%3};"
        : "+f"(c[0]), "+f"(c[1]), "+f"(c[2]), "+f"(c[3])
        : "r"(a[0]), "r"(a[1]), "r"(a[2]), "r"(a[3]), "r"(b0), "r"(b1));
}

// ---------------------------------------------------------------------------
// Kernel 1: QKV projection with tf32 mma. 1024 CTAs x 256 thr.
// Warp does a 16-row tile over all K=192, all 64 out cols, all 3 weights.
// W staged tf32 in smem, row stride 72 (72 mod 32 = 8 -> B-frag banks 8k+n).
// ---------------------------------------------------------------------------
#define WS 72
__global__ __launch_bounds__(256) void qkv_mma_kernel(const float* __restrict__ x,
                                                      const float* __restrict__ Wq,
                                                      const float* __restrict__ Wk,
                                                      const float* __restrict__ Wv) {
    extern __shared__ float W_s[];   // [3][192][72] = 41472 floats
    const int tid = threadIdx.x;

    for (int f = tid; f < 9216; f += 256) {           // 3*192*16 float4 loads
        int sel = f / 3072, r = f % 3072;
        int k = r >> 4, n4 = r & 15;
        const float* __restrict__ W = (sel == 0) ? Wq : ((sel == 1) ? Wk : Wv);
        float4 v = *(const float4*)(W + k * 64 + n4 * 4);
        float* d = W_s + sel * (192 * WS) + k * WS + n4 * 4;
        d[0] = __uint_as_float(f2tf(v.x));
        d[1] = __uint_as_float(f2tf(v.y));
        d[2] = __uint_as_float(f2tf(v.z));
        d[3] = __uint_as_float(f2tf(v.w));
    }
    __syncthreads();

    const int w = tid >> 5, lane = tid & 31;
    const int gq = lane >> 2, tg = lane & 3;
    const int row0 = blockIdx.x * 128 + w * 16;
    const float* __restrict__ xb = x + (size_t)row0 * 192;

    float acc[3][8][4];
#pragma unroll
    for (int s = 0; s < 3; s++)
#pragma unroll
        for (int n = 0; n < 8; n++)
#pragma unroll
            for (int i = 0; i < 4; i++) acc[s][n][i] = 0.0f;

    unsigned a[4], an[4];
    a[0] = f2tf(xb[gq * 192 + tg]);
    a[1] = f2tf(xb[(gq + 8) * 192 + tg]);
    a[2] = f2tf(xb[gq * 192 + tg + 4]);
    a[3] = f2tf(xb[(gq + 8) * 192 + tg + 4]);

    for (int kk = 0; kk < 24; kk++) {
        if (kk < 23) {
            int kb = (kk + 1) * 8;
            an[0] = f2tf(xb[gq * 192 + kb + tg]);
            an[1] = f2tf(xb[(gq + 8) * 192 + kb + tg]);
            an[2] = f2tf(xb[gq * 192 + kb + tg + 4]);
            an[3] = f2tf(xb[(gq + 8) * 192 + kb + tg + 4]);
        }
        const float* wb = W_s + (kk * 8 + tg) * WS + gq;   // b0 base addr
#pragma unroll
        for (int sel = 0; sel < 3; sel++) {
            const float* ws = wb + sel * (192 * WS);
#pragma unroll
            for (int nt = 0; nt < 8; nt++) {
                unsigned b0 = __float_as_uint(ws[nt * 8]);
                unsigned b1 = __float_as_uint(ws[4 * WS + nt * 8]);
                mma_tf32(acc[sel][nt], a, b0, b1);
            }
        }
        a[0] = an[0]; a[1] = an[1]; a[2] = an[2]; a[3] = an[3];
    }

    // Epilogue. q row-major; k,v transposed [b][h][t].
    const int bb = row0 >> 8;
    const int t0 = (row0 & 255) + gq;
    float* qout = g_q + (size_t)row0 * 64;
    float* kb_ = g_kT + (size_t)bb * 16384;
    float* vb_ = g_vT + (size_t)bb * 16384;
#pragma unroll
    for (int nt = 0; nt < 8; nt++) {
        int col = nt * 8 + 2 * tg;
        *(float2*)(qout + (size_t)gq * 64 + col) = make_float2(acc[0][nt][0], acc[0][nt][1]);
        *(float2*)(qout + (size_t)(gq + 8) * 64 + col) = make_float2(acc[0][nt][2], acc[0][nt][3]);
        kb_[col * 256 + t0]           = acc[1][nt][0];
        kb_[(col + 1) * 256 + t0]     = acc[1][nt][1];
        kb_[col * 256 + t0 + 8]       = acc[1][nt][2];
        kb_[(col + 1) * 256 + t0 + 8] = acc[1][nt][3];
        vb_[col * 256 + t0]           = acc[2][nt][0];
        vb_[(col + 1) * 256 + t0]     = acc[2][nt][1];
        vb_[col * 256 + t0 + 8]       = acc[2][nt][2];
        vb_[(col + 1) * 256 + t0 + 8] = acc[2][nt][3];
    }
}

// ---------------------------------------------------------------------------
// Kernel 2 + 3: positional projections and bias (tiny, fp32 exact)
// ---------------------------------------------------------------------------
__global__ __launch_bounds__(256) void pos_kernel(const float* __restrict__ pe,
                                                  const float* __restrict__ Wk,
                                                  const float* __restrict__ Wq) {
    int idx = blockIdx.x * 256 + threadIdx.x;
    int t = idx >> 7;
    int j = idx & 127;
    const float* __restrict__ W = (j < 64) ? Wk : Wq;
    int col = j & 63;
    float s = 0.0f;
#pragma unroll 4
    for (int c = 0; c < 192; c++) s = fmaf(pe[t * 192 + c], W[c * 64 + col], s);
    g_pos[idx] = s;
}

__global__ __launch_bounds__(256) void bias_kernel() {
    int i = blockIdx.x;
    int j = threadIdx.x;
    float s = 0.0f;
#pragma unroll 4
    for (int h = 0; h < 64; h++)
        s = fmaf(g_pos[i * 128 + h], g_pos[j * 128 + 64 + h], s);
    g_bias[i * 256 + j] = s;
}

// ---------------------------------------------------------------------------
// Kernel 4: flash attention with tf32 mma. One CTA per batch, 8 warps.
// K^T,V^T staged tf32 in smem stride 264 (mod 32 = 8 -> conflict-free frags).
// Warp w handles q-tiles {w, 15-w} (balanced 17 j-tiles each).
// ---------------------------------------------------------------------------
#define KVS 264
__global__ __launch_bounds__(256) void attn_mma_kernel(float* __restrict__ out) {
    extern __shared__ float sm[];
    float* k_s = sm;                       // [64][264]
    float* v_s = sm + 64 * KVS;            // [64][264]
    float* p_s = sm + 2 * 64 * KVS;        // [8][16][20]

    const int b = blockIdx.x;
    const int tid = threadIdx.x, w = tid >> 5, lane = tid & 31;
    const int gq = lane >> 2, tg = lane & 3;

    // Stage K^T, V^T (coalesced reads, conflict-free v4 stores), tf32-convert.
    const float* __restrict__ kg = g_kT + (size_t)b * 16384;
    const float* __restrict__ vg = g_vT + (size_t)b * 16384;
    for (int f = tid; f < 4096; f += 256) {
        int h = f >> 6, t4 = (f & 63) * 4;
        float4 kv = *(const float4*)(kg + h * 256 + t4);
        float4 vv = *(const float4*)(vg + h * 256 + t4);
        float* kd = k_s + h * KVS + t4;
        kd[0] = __uint_as_float(f2tf(kv.x));
        kd[1] = __uint_as_float(f2tf(kv.y));
        kd[2] = __uint_as_float(f2tf(kv.z));
        kd[3] = __uint_as_float(f2tf(kv.w));
        float* vd = v_s + h * KVS + t4;
        vd[0] = __uint_as_float(f2tf(vv.x));
        vd[1] = __uint_as_float(f2tf(vv.y));
        vd[2] = __uint_as_float(f2tf(vv.z));
        vd[3] = __uint_as_float(f2tf(vv.w));
    }
    __syncthreads();

    float* pw = p_s + w * 320;
    const float scale = rsqrtf(192.0f);

    for (int pass = 0; pass < 2; pass++) {
        const int qt = pass ? (15 - w) : w;
        const int r0 = qt * 16;

        // Q fragments for all 8 k-steps (held in registers)
        unsigned qa[8][4];
        const float* __restrict__ qg = g_q + ((size_t)b * 256 + r0) * 64;
#pragma unroll
        for (int kk = 0; kk < 8; kk++) {
            int c = kk * 8 + tg;
            qa[kk][0] = f2tf(qg[gq * 64 + c]);
            qa[kk][1] = f2tf(qg[(gq + 8) * 64 + c]);
            qa[kk][2] = f2tf(qg[gq * 64 + c + 4]);
            qa[kk][3] = f2tf(qg[(gq + 8) * 64 + c + 4]);
        }

        float o[8][4];
#pragma unroll
        for (int n = 0; n < 8; n++)
#pragma unroll
            for (int i = 0; i < 4; i++) o[n][i] = 0.0f;
        float m0 = -1e30f, m1 = -1e30f, l0 = 0.0f, l1 = 0.0f;

        for (int jt = 0; jt <= qt; jt++) {
            const int j0 = jt * 16;
            float s[2][4];
#pragma unroll
            for (int n = 0; n < 2; n++)
#pragma unroll
                for (int i = 0; i < 4; i++) s[n][i] = 0.0f;

            // S = Q K^T
#pragma unroll
            for (int kk = 0; kk < 8; kk++) {
                const float* kb2 = k_s + (kk * 8 + tg) * KVS + j0 + gq;
#pragma unroll
                for (int nt = 0; nt < 2; nt++) {
                    unsigned b0 = __float_as_uint(kb2[nt * 8]);
                    unsigned b1 = __float_as_uint(kb2[4 * KVS + nt * 8]);
                    mma_tf32(s[nt], qa[kk], b0, b1);
                }
            }

            // scale + bias + causal mask
            const int rowg = r0 + gq;
            const float* __restrict__ br0 = g_bias + rowg * 256 + j0;
            const float* __restrict__ br1 = br0 + 8 * 256;
#pragma unroll
            for (int nt = 0; nt < 2; nt++) {
                int c = nt * 8 + 2 * tg;
                float2 bias0 = *(const float2*)(br0 + c);
                float2 bias1 = *(const float2*)(br1 + c);
                s[nt][0] = fmaf(s[nt][0], scale, bias0.x);
                s[nt][1] = fmaf(s[nt][1], scale, bias0.y);
                s[nt][2] = fmaf(s[nt][2], scale, bias1.x);
                s[nt][3] = fmaf(s[nt][3], scale, bias1.y);
                if (jt == qt) {
                    int col = j0 + c;
                    if (col > rowg)         s[nt][0] = -1e30f;
                    if (col + 1 > rowg)     s[nt][1] = -1e30f;
                    if (col > rowg + 8)     s[nt][2] = -1e30f;
                    if (col + 1 > rowg + 8) s[nt][3] = -1e30f;
                }
            }

            // online softmax update
            float mx0 = fmaxf(fmaxf(s[0][0], s[0][1]), fmaxf(s[1][0], s[1][1]));
            float mx1 = fmaxf(fmaxf(s[0][2], s[0][3]), fmaxf(s[1][2], s[1][3]));
            mx0 = fmaxf(mx0, __shfl_xor_sync(0xffffffffu, mx0, 1));
            mx0 = fmaxf(mx0, __shfl_xor_sync(0xffffffffu, mx0, 2));
            mx1 = fmaxf(mx1, __shfl_xor_sync(0xffffffffu, mx1, 1));
            mx1 = fmaxf(mx1, __shfl_xor_sync(0xffffffffu, mx1, 2));
            float mn0 = fmaxf(m0, mx0), mn1 = fmaxf(m1, mx1);
            float al0 = __expf(m0 - mn0), al1 = __expf(m1 - mn1);
            m0 = mn0; m1 = mn1;

            float e00 = __expf(s[0][0] - mn0), e01 = __expf(s[0][1] - mn0);
            float e10 = __expf(s[1][0] - mn0), e11 = __expf(s[1][1] - mn0);
            float e02 = __expf(s[0][2] - mn1), e03 = __expf(s[0][3] - mn1);
            float e12 = __expf(s[1][2] - mn1), e13 = __expf(s[1][3] - mn1);

            float sum0 = (e00 + e01) + (e10 + e11);
            float sum1 = (e02 + e03) + (e12 + e13);
            sum0 += __shfl_xor_sync(0xffffffffu, sum0, 1);
            sum0 += __shfl_xor_sync(0xffffffffu, sum0, 2);
            sum1 += __shfl_xor_sync(0xffffffffu, sum1, 1);
            sum1 += __shfl_xor_sync(0xffffffffu, sum1, 2);
            l0 = l0 * al0 + sum0;
            l1 = l1 * al1 + sum1;

#pragma unroll
            for (int nt = 0; nt < 8; nt++) {
                o[nt][0] *= al0; o[nt][1] *= al0;
                o[nt][2] *= al1; o[nt][3] *= al1;
            }

            // stage P (tf32) to per-warp smem, stride 20 (conflict-free A-frags)
            *(float2*)(pw + gq * 20 + 2 * tg) =
                make_float2(__uint_as_float(f2tf(e00)), __uint_as_float(f2tf(e01)));
            *(float2*)(pw + gq * 20 + 8 + 2 * tg) =
                make_float2(__uint_as_float(f2tf(e10)), __uint_as_float(f2tf(e11)));
            *(float2*)(pw + (gq + 8) * 20 + 2 * tg) =
                make_float2(__uint_as_float(f2tf(e02)), __uint_as_float(f2tf(e03)));
            *(float2*)(pw + (gq + 8) * 20 + 8 + 2 * tg) =
                make_float2(__uint_as_float(f2tf(e12)), __uint_as_float(f2tf(e13)));
            __syncwarp();

            // O += P V
#pragma unroll
            for (int ks = 0; ks < 2; ks++) {
                unsigned pa[4];
                pa[0] = __float_as_uint(pw[gq * 20 + ks * 8 + tg]);
                pa[1] = __float_as_uint(pw[(gq + 8) * 20 + ks * 8 + tg]);
                pa[2] = __float_as_uint(pw[gq * 20 + ks * 8 + tg + 4]);
                pa[3] = __float_as_uint(pw[(gq + 8) * 20 + ks * 8 + tg + 4]);
#pragma unroll
                for (int nt = 0; nt < 8; nt++) {
                    const float* vb2 = v_s + (nt * 8 + gq) * KVS + j0 + ks * 8 + tg;
                    unsigned b0 = __float_as_uint(vb2[0]);
                    unsigned b1 = __float_as_uint(vb2[4]);
                    mma_tf32(o[nt], pa, b0, b1);
                }
            }
            __syncwarp();
        }

        float inv0 = 1.0f / l0, inv1 = 1.0f / l1;
        float* ob = out + ((size_t)b * 256 + r0) * 64;
#pragma unroll
        for (int nt = 0; nt < 8; nt++) {
            int c = nt * 8 + 2 * tg;
            *(float2*)(ob + gq * 64 + c) = make_float2(o[nt][0] * inv0, o[nt][1] * inv0);
            *(float2*)(ob + (gq + 8) * 64 + c) = make_float2(o[nt][2] * inv1, o[nt][3] * inv1);
        }
    }
}

// ---------------------------------------------------------------------------
extern "C" void kernel_launch(void* const* d_in, const int* in_sizes, int n_in,
                              void* d_out, int out_size) {
    const float* x  = (const float*)d_in[0];
    const float* Wk = (const float*)d_in[1];
    const float* Wq = (const float*)d_in[2];
    const float* Wv = (const float*)d_in[3];
    const float* pe = (const float*)d_in[4];
    float* out = (float*)d_out;
    (void)in_sizes; (void)n_in; (void)out_size;

    static bool attr_set = false;
    if (!attr_set) {
        cudaFuncSetAttribute(qkv_mma_kernel,
                             cudaFuncAttributeMaxDynamicSharedMemorySize, 165888);
        cudaFuncSetAttribute(attn_mma_kernel,
                             cudaFuncAttributeMaxDynamicSharedMemorySize, 145408);
        attr_set = true;
    }

    qkv_mma_kernel<<<1024, 256, 165888>>>(x, Wq, Wk, Wv);
    pos_kernel<<<128, 256>>>(pe, Wk, Wq);
    bias_kernel<<<256, 256>>>();
    attn_mma_kernel<<<512, 256, 145408>>>(out);
}